// round 16
// baseline (speedup 1.0000x reference)
#include <cuda_runtime.h>
#include <cuda.h>
#include <cuda_fp16.h>
#include <cstdint>
#include <cmath>

// Problem constants
#define T_TOK 1024
#define HDIM  2048
#define NEXP  64
#define IDIM  1024
#define SIDIM 4096
#define KSEL  8
#define NROWS (T_TOK * KSEL)
#define EPH   (NEXP / 2)                       // 32 experts per half

// Tile config: CTA 128x128, 8 warps (4Mx2N), warp tile 32x64, fp16 BK=64.
#define BM 128
#define BN 128
#define NSTAGE 3
#define STG_B   32768                          // bytes per stage (A 16KB + B 16KB)
#define MBOFF   (NSTAGE * STG_B)               // 98304
#define GS_DENSE (MBOFF + 64 + 128)            // 98496

// ---------------------------------------------------------------------------
// Device-global scratch
// ---------------------------------------------------------------------------
__device__ __align__(256) __half g_w13h[(size_t)NEXP * 2 * IDIM * HDIM]; // 512MB
__device__ __align__(256) __half g_w2h [(size_t)NEXP * HDIM * IDIM];     // 256MB
__device__ __align__(256) __half g_wsgh[(size_t)2 * SIDIM * HDIM];       // 32MB
__device__ __align__(256) __half g_wsdh[(size_t)HDIM * SIDIM];           // 16MB
__device__ __align__(256) __half g_xh  [(size_t)T_TOK * HDIM];           // 4MB
__device__ __align__(256) __half g_xg  [(size_t)NROWS * HDIM];           // 32MB gathered x
__device__ __align__(256) __half g_h   [(size_t)NROWS * IDIM];
__device__ __align__(256) __half g_h_s [(size_t)T_TOK * SIDIM];
__device__ __align__(256) float  g_down[(size_t)NROWS * HDIM];
__device__ __align__(256) float  g_sh_out[(size_t)T_TOK * HDIM];

__device__ int   g_counts[NEXP];
__device__ int   g_offsets[NEXP];
__device__ int   g_fill[NEXP];
__device__ int   g_rowmap[NROWS];
__device__ int   g_row_of_tk[NROWS];
__device__ int   g_top_e[NROWS];
__device__ float g_top_w[NROWS];
__device__ int   g_ticket;

// ---------------------------------------------------------------------------
// Helpers
// ---------------------------------------------------------------------------
#define MBARRIER_INIT(addr, cnt) \
    asm volatile("mbarrier.init.shared.b64 [%0], %1;" :: "r"((uint32_t)(addr)), "r"((uint32_t)(cnt)) : "memory")

#define MBARRIER_EXPECT_TX(addr, bytes) \
    asm volatile("mbarrier.arrive.expect_tx.shared.b64 _, [%0], %1;" \
        :: "r"((uint32_t)(addr)), "r"((uint32_t)(bytes)) : "memory")

#define MBARRIER_WAIT_PARITY(addr, parity) do {                                         \
    uint32_t _m = (uint32_t)(addr); uint32_t _p = (uint32_t)(parity); uint32_t _d;      \
    asm volatile("{ .reg .pred p; mbarrier.try_wait.parity.acquire.cta.shared::cta.b64 p, [%1], %2; selp.b32 %0,1,0,p; }" \
        : "=r"(_d) : "r"(_m), "r"(_p) : "memory");                                      \
    if (!_d) {                                                                          \
        asm volatile("{ .reg .pred P1; WL_%=: mbarrier.try_wait.parity.acquire.cta.shared::cta.b64 P1, [%0], %1, 0x989680; @P1 bra.uni WD_%=; bra.uni WL_%=; WD_%=: }" \
            :: "r"(_m), "r"(_p) : "memory");                                            \
    }                                                                                   \
} while (0)

#define FENCE_ASYNC() asm volatile("fence.proxy.async.shared::cta;" ::: "memory")

__device__ __forceinline__ void tma2d(uint32_t dst, const CUtensorMap* tm, int x, int y, uint32_t mbar) {
    asm volatile("cp.async.bulk.tensor.2d.shared::cta.global.tile.mbarrier::complete_tx::bytes "
                 "[%0], [%1, {%2, %3}], [%4];"
                 :: "r"(dst), "l"(tm), "r"(x), "r"(y), "r"(mbar) : "memory");
}

__device__ __forceinline__ void ldm_x4(uint32_t& r0, uint32_t& r1, uint32_t& r2, uint32_t& r3,
                                       uint32_t addr) {
    asm volatile("ldmatrix.sync.aligned.m8n8.x4.shared.b16 {%0,%1,%2,%3}, [%4];"
                 : "=r"(r0), "=r"(r1), "=r"(r2), "=r"(r3) : "r"(addr));
}

__device__ __forceinline__ void mma_f16(float c[4],
                                        uint32_t a0, uint32_t a1, uint32_t a2, uint32_t a3,
                                        uint32_t b0, uint32_t b1) {
    asm volatile(
        "mma.sync.aligned.m16n8k16.row.col.f32.f16.f16.f32 "
        "{%0,%1,%2,%3},{%4,%5,%6,%7},{%8,%9},{%0,%1,%2,%3};\n"
        : "+f"(c[0]), "+f"(c[1]), "+f"(c[2]), "+f"(c[3])
        : "r"(a0), "r"(a1), "r"(a2), "r"(a3), "r"(b0), "r"(b1));
}

__device__ __forceinline__ float silu_mul(float g, float u) {
    return g * u / (1.f + expf(-g));
}

// ---------------------------------------------------------------------------
// fp32 -> fp16 convert kernels
// ---------------------------------------------------------------------------
__global__ void cvt_k(const float4* __restrict__ in, uint2* __restrict__ outp, long n4) {
    long i = (long)blockIdx.x * blockDim.x + threadIdx.x;
    long stride = (long)gridDim.x * blockDim.x;
    for (; i < n4; i += stride) {
        float4 v = in[i];
        __half2 h0 = __floats2half2_rn(v.x, v.y);
        __half2 h1 = __floats2half2_rn(v.z, v.w);
        uint2 o;
        o.x = *(uint32_t*)&h0;
        o.y = *(uint32_t*)&h1;
        outp[i] = o;
    }
}

__global__ void cvt_init_k(const float4* __restrict__ in, uint2* __restrict__ outp, long n4) {
    if (blockIdx.x == 0 && threadIdx.x < NEXP) g_counts[threadIdx.x] = 0;
    long i = (long)blockIdx.x * blockDim.x + threadIdx.x;
    long stride = (long)gridDim.x * blockDim.x;
    for (; i < n4; i += stride) {
        float4 v = in[i];
        __half2 h0 = __floats2half2_rn(v.x, v.y);
        __half2 h1 = __floats2half2_rn(v.z, v.w);
        uint2 o;
        o.x = *(uint32_t*)&h0;
        o.y = *(uint32_t*)&h1;
        outp[i] = o;
    }
}

// ---------------------------------------------------------------------------
// Fused router + scan + assign (ticket: last block finalizes)
// ---------------------------------------------------------------------------
__global__ void router_fused_k(const float* __restrict__ x, const float* __restrict__ wg) {
    int t = blockIdx.x;
    __shared__ float xs[HDIM];
    __shared__ float sc[NEXP];
    __shared__ int isLast;
    for (int d = threadIdx.x; d < HDIM; d += blockDim.x) xs[d] = x[(size_t)t * HDIM + d];
    __syncthreads();

    int w = threadIdx.x >> 5, lane = threadIdx.x & 31;
    for (int e = w * 8; e < w * 8 + 8; e++) {
        const float* wr = wg + (size_t)e * HDIM;
        float s = 0.f;
        for (int d = lane; d < HDIM; d += 32) s += xs[d] * wr[d];
        #pragma unroll
        for (int o = 16; o; o >>= 1) s += __shfl_xor_sync(0xffffffffu, s, o);
        if (lane == 0) sc[e] = 1.f / (1.f + expf(-s));
    }
    __syncthreads();

    if (threadIdx.x == 0) {
        for (int k = 0; k < KSEL; k++) {
            int best = 0; float bv = sc[0];
            for (int e = 1; e < NEXP; e++)
                if (sc[e] > bv) { bv = sc[e]; best = e; }
            g_top_e[t * KSEL + k] = best;
            g_top_w[t * KSEL + k] = bv;
            atomicAdd(&g_counts[best], 1);
            sc[best] = -1.f;
        }
    }

    __threadfence();
    if (threadIdx.x == 0) {
        int tk = atomicAdd(&g_ticket, 1);
        isLast = (tk == (int)gridDim.x - 1);
        if (isLast) g_ticket = 0;
    }
    __syncthreads();
    if (!isLast) return;

    if (threadIdx.x == 0) {
        int acc = 0;
        for (int e = 0; e < NEXP; e++) {
            g_offsets[e] = acc;
            g_fill[e] = acc;
            acc += g_counts[e];
        }
    }
    __syncthreads();
    for (int idx = threadIdx.x; idx < NROWS; idx += blockDim.x) {
        int e = g_top_e[idx];
        int r = atomicAdd(&g_fill[e], 1);
        g_rowmap[r] = idx >> 3;
        g_row_of_tk[idx] = r;
    }
}

// ---------------------------------------------------------------------------
// gather_k — materialize gathered A: g_xg[r] = g_xh[rowmap[r]]
// ---------------------------------------------------------------------------
__global__ void gather_k() {
    int r = blockIdx.x;
    int src = g_rowmap[r];
    const uint4* s = (const uint4*)(g_xh + (size_t)src * HDIM);
    uint4* d = (uint4*)(g_xg + (size_t)r * HDIM);
    d[threadIdx.x] = s[threadIdx.x];
}

// ---------------------------------------------------------------------------
// gemm10 — FP16 mma.sync, all operands via TMA (SW128 = verified c^(r&7)).
// CTA 128x128, 8 warps (4Mx2N), warp tile 32x64, BK=64 fp16, 3-stage ring.
// ---------------------------------------------------------------------------
template <bool EXPERT, bool ACT>
__global__ void __launch_bounds__(256, 2)
gemm10(const __grid_constant__ CUtensorMap tmA,
       const __grid_constant__ CUtensorMap tmB,
       void* __restrict__ Cv,
       int Kd, int Nout, int rowsBe, int upOff, int Mdense, int eBase)
{
    extern __shared__ char sm[];
    int e = EXPERT ? (eBase + blockIdx.z) : 0;
    int M, off;
    if (EXPERT) { M = g_counts[e]; off = g_offsets[e]; }
    else        { M = Mdense;      off = 0; }
    int m0 = blockIdx.y * BM;
    if (m0 >= M) return;
    int nb = blockIdx.x;

    int tid = threadIdx.x, warp = tid >> 5, lane = tid & 31;
    uint32_t smem_base = (uint32_t)__cvta_generic_to_shared(sm);
    const CUtensorMap* tmAp = &tmA;
    const CUtensorMap* tmBp = &tmB;
    int rowBase = EXPERT ? e * rowsBe : 0;
    int aRow0 = off + m0;

    if (tid == 0) {
        #pragma unroll
        for (int s = 0; s < NSTAGE; s++) MBARRIER_INIT(smem_base + MBOFF + s * 8, 1);
        FENCE_ASYNC();
    }
    __syncthreads();

    auto stage_issue = [&](int kt, int s) {
        if (tid == 0) {
            uint32_t mb = smem_base + (uint32_t)(MBOFF + s * 8);
            uint32_t stg = smem_base + (uint32_t)(s * STG_B);
            int k0 = kt * 64;
            MBARRIER_EXPECT_TX(mb, STG_B);
            tma2d(stg, tmAp, k0, aRow0, mb);
            if (ACT) {
                tma2d(stg + 16384,            tmBp, k0, rowBase + nb * 64,         mb);
                tma2d(stg + 16384 + 64 * 128, tmBp, k0, rowBase + upOff + nb * 64, mb);
            } else {
                tma2d(stg + 16384, tmBp, k0, rowBase + nb * BN, mb);
            }
        }
    };

    int wm = warp & 3;
    int wn = warp >> 2;
    int g  = lane >> 2, tg = lane & 3;

    int aro  = (lane & 7) + ((lane >> 3) & 1) * 8;
    int acs  = (lane >> 4) & 1;
    int bro  = (lane & 7) + ((lane >> 4) & 1) * 8;
    int bcs  = (lane >> 3) & 1;

    uint32_t aRow[2], aMod[2];
    #pragma unroll
    for (int mi = 0; mi < 2; mi++) {
        int r = wm * 32 + mi * 16 + aro;
        aRow[mi] = (uint32_t)(r * 128);
        aMod[mi] = (uint32_t)(r & 7);
    }
    uint32_t bRow[4], bMod[4];
    #pragma unroll
    for (int p = 0; p < 4; p++) {
        int base;
        if (ACT) base = (p < 2) ? (wn * 32 + p * 16) : (64 + wn * 32 + (p - 2) * 16);
        else     base = wn * 64 + p * 16;
        int r = base + bro;
        bRow[p] = (uint32_t)(16384 + r * 128);
        bMod[p] = (uint32_t)(r & 7);
    }

    float acc[2][8][4];
    #pragma unroll
    for (int i = 0; i < 2; i++)
        #pragma unroll
        for (int j = 0; j < 8; j++)
            #pragma unroll
            for (int q = 0; q < 4; q++) acc[i][j][q] = 0.f;

    int ktiles = Kd / 64;
    stage_issue(0, 0);
    stage_issue(1, 1);
    uint32_t phases = 0;

    for (int kt = 0; kt < ktiles; kt++) {
        int s = kt % NSTAGE;
        uint32_t mb = smem_base + (uint32_t)(MBOFF + s * 8);
        MBARRIER_WAIT_PARITY(mb, (phases >> s) & 1);
        phases ^= (1u << s);
        uint32_t stg = smem_base + (uint32_t)(s * STG_B);

        #pragma unroll
        for (int kk = 0; kk < 4; kk++) {
            uint32_t c0 = (uint32_t)(kk * 2);

            uint32_t afr[2][4];
            #pragma unroll
            for (int mi = 0; mi < 2; mi++) {
                uint32_t addr = stg + aRow[mi] + ((((c0 + acs) ^ aMod[mi])) << 4);
                ldm_x4(afr[mi][0], afr[mi][1], afr[mi][2], afr[mi][3], addr);
            }
            uint32_t bfr[4][4];
            #pragma unroll
            for (int p = 0; p < 4; p++) {
                uint32_t addr = stg + bRow[p] + ((((c0 + bcs) ^ bMod[p])) << 4);
                ldm_x4(bfr[p][0], bfr[p][1], bfr[p][2], bfr[p][3], addr);
            }
            #pragma unroll
            for (int p = 0; p < 4; p++) {
                #pragma unroll
                for (int h = 0; h < 2; h++) {
                    int ni = p * 2 + h;
                    uint32_t b0 = bfr[p][2 * h], b1 = bfr[p][2 * h + 1];
                    mma_f16(acc[0][ni], afr[0][0], afr[0][1], afr[0][2], afr[0][3], b0, b1);
                    mma_f16(acc[1][ni], afr[1][0], afr[1][1], afr[1][2], afr[1][3], b0, b1);
                }
            }
        }
        __syncthreads();
        if (kt + 2 < ktiles) stage_issue(kt + 2, (kt + 2) % NSTAGE);
    }

    // ---- epilogue
    #pragma unroll
    for (int mi = 0; mi < 2; mi++) {
        int r0 = m0 + wm * 32 + mi * 16 + g;
        bool v0 = r0 < M, v1 = (r0 + 8) < M;
        size_t base0 = (size_t)(off + r0) * Nout;
        size_t base1 = (size_t)(off + r0 + 8) * Nout;
        if (ACT) {
            __half* Ch = (__half*)Cv;
            #pragma unroll
            for (int ni = 0; ni < 4; ni++) {
                int col = nb * 64 + wn * 32 + ni * 8 + tg * 2;
                if (v0) {
                    __half2 o = __floats2half2_rn(
                        silu_mul(acc[mi][ni][0], acc[mi][ni + 4][0]),
                        silu_mul(acc[mi][ni][1], acc[mi][ni + 4][1]));
                    *(__half2*)(Ch + base0 + col) = o;
                }
                if (v1) {
                    __half2 o = __floats2half2_rn(
                        silu_mul(acc[mi][ni][2], acc[mi][ni + 4][2]),
                        silu_mul(acc[mi][ni][3], acc[mi][ni + 4][3]));
                    *(__half2*)(Ch + base1 + col) = o;
                }
            }
        } else {
            float* Cf = (float*)Cv;
            #pragma unroll
            for (int ni = 0; ni < 8; ni++) {
                int col = nb * BN + wn * 64 + ni * 8 + tg * 2;
                if (v0) {
                    float2 o; o.x = acc[mi][ni][0]; o.y = acc[mi][ni][1];
                    *(float2*)(Cf + base0 + col) = o;
                }
                if (v1) {
                    float2 o; o.x = acc[mi][ni][2]; o.y = acc[mi][ni][3];
                    *(float2*)(Cf + base1 + col) = o;
                }
            }
        }
    }
}

// ---------------------------------------------------------------------------
// Combine
// ---------------------------------------------------------------------------
__global__ void combine_k(float* __restrict__ out) {
    int t = blockIdx.x;
    __shared__ int   rws[KSEL];
    __shared__ float ws[KSEL];
    if (threadIdx.x < KSEL) {
        rws[threadIdx.x] = g_row_of_tk[t * KSEL + threadIdx.x];
        ws[threadIdx.x]  = g_top_w[t * KSEL + threadIdx.x];
    }
    __syncthreads();
    for (int d = threadIdx.x; d < HDIM; d += blockDim.x) {
        float a = g_sh_out[(size_t)t * HDIM + d];
        float m = 0.f;
        #pragma unroll
        for (int k = 0; k < KSEL; k++)
            m += ws[k] * g_down[(size_t)rws[k] * HDIM + d];
        out[(size_t)t * HDIM + d] = (a + 8.f * m) * (1.f / 9.f);
    }
}

// ---------------------------------------------------------------------------
// kernel_launch — graph-capturable, allocation-free, THREE-stream DAG
// (graph kept small: 16 nodes / 8 events to stay under the harness's
//  graph-upload allocation threshold seen in round 15):
//  s0: cvt_x | router | gather | [w13h0] gu0 | [w13h1] gu1 | [down,join] combine
//  s2: cvt w13h0 | cvt w2h0 | cvt w13h1 | cvt w2h1 | [gu0] down0 | [gu1] down1
//  s3: cvt wsg | cvt wsd | [x] sh_gu | sh_down
// ---------------------------------------------------------------------------
typedef CUresult (CUDAAPI *PFN_encodeTiled)(
    CUtensorMap*, CUtensorMapDataType, cuuint32_t, void*,
    const cuuint64_t*, const cuuint64_t*, const cuuint32_t*, const cuuint32_t*,
    CUtensorMapInterleave, CUtensorMapSwizzle, CUtensorMapL2promotion,
    CUtensorMapFloatOOBfill);

extern "C" void kernel_launch(void* const* d_in, const int* in_sizes, int n_in,
                              void* d_out, int out_size)
{
    const float* x      = (const float*)d_in[0];
    const float* w_gate = (const float*)d_in[1];
    const float* w13    = (const float*)d_in[2];
    const float* w2     = (const float*)d_in[3];
    const float* wsg    = (const float*)d_in[4];
    const float* wsd    = (const float*)d_in[5];
    float* out = (float*)d_out;

    __half *p_w13h, *p_w2h, *p_wsgh, *p_wsdh, *p_xh, *p_xg, *p_h, *p_h_s;
    float  *p_down, *p_sh_out;
    cudaGetSymbolAddress((void**)&p_w13h,   g_w13h);
    cudaGetSymbolAddress((void**)&p_w2h,    g_w2h);
    cudaGetSymbolAddress((void**)&p_wsgh,   g_wsgh);
    cudaGetSymbolAddress((void**)&p_wsdh,   g_wsdh);
    cudaGetSymbolAddress((void**)&p_xh,     g_xh);
    cudaGetSymbolAddress((void**)&p_xg,     g_xg);
    cudaGetSymbolAddress((void**)&p_h,      g_h);
    cudaGetSymbolAddress((void**)&p_h_s,    g_h_s);
    cudaGetSymbolAddress((void**)&p_down,   g_down);
    cudaGetSymbolAddress((void**)&p_sh_out, g_sh_out);

    static bool tmInit = false;
    static CUtensorMap tmXh, tmXg, tmH, tmHs, tmW13, tmW2, tmWsg, tmWsd;
    if (!tmInit) {
        PFN_encodeTiled enc = nullptr;
        cudaDriverEntryPointQueryResult qr;
        cudaGetDriverEntryPoint("cuTensorMapEncodeTiled", (void**)&enc, cudaEnableDefault, &qr);
        auto mk = [&](CUtensorMap* tm, void* ptr, unsigned long long d0, unsigned long long d1,
                      unsigned b0, unsigned b1) {
            cuuint64_t dims[2]    = {d0, d1};
            cuuint64_t strides[1] = {d0 * 2};
            cuuint32_t box[2]     = {b0, b1};
            cuuint32_t es[2]      = {1, 1};
            enc(tm, CU_TENSOR_MAP_DATA_TYPE_FLOAT16, 2, ptr, dims, strides, box, es,
                CU_TENSOR_MAP_INTERLEAVE_NONE, CU_TENSOR_MAP_SWIZZLE_128B,
                CU_TENSOR_MAP_L2_PROMOTION_L2_128B, CU_TENSOR_MAP_FLOAT_OOB_FILL_NONE);
        };
        mk(&tmXh,  p_xh,   HDIM,  T_TOK,                               64, 128);
        mk(&tmXg,  p_xg,   HDIM,  NROWS,                               64, 128);
        mk(&tmH,   p_h,    IDIM,  NROWS,                               64, 128);
        mk(&tmHs,  p_h_s,  SIDIM, T_TOK,                               64, 128);
        mk(&tmW13, p_w13h, HDIM,  (unsigned long long)NEXP * 2 * IDIM, 64, 64);
        mk(&tmW2,  p_w2h,  IDIM,  (unsigned long long)NEXP * HDIM,     64, 128);
        mk(&tmWsg, p_wsgh, HDIM,  2 * SIDIM,                           64, 64);
        mk(&tmWsd, p_wsdh, SIDIM, HDIM,                                64, 128);
        tmInit = true;
    }

    cudaFuncSetAttribute(gemm10<true,  true >, cudaFuncAttributeMaxDynamicSharedMemorySize, GS_DENSE);
    cudaFuncSetAttribute(gemm10<true,  false>, cudaFuncAttributeMaxDynamicSharedMemorySize, GS_DENSE);
    cudaFuncSetAttribute(gemm10<false, true >, cudaFuncAttributeMaxDynamicSharedMemorySize, GS_DENSE);
    cudaFuncSetAttribute(gemm10<false, false>, cudaFuncAttributeMaxDynamicSharedMemorySize, GS_DENSE);

    static cudaStream_t s2 = nullptr, s3 = nullptr;
    static cudaEvent_t evFork = nullptr, evX = nullptr, evW13a = nullptr, evW13b = nullptr,
                       evGu0 = nullptr, evGu1 = nullptr, evDown = nullptr, evJoin = nullptr;
    if (!s2) {
        cudaStreamCreateWithFlags(&s2, cudaStreamNonBlocking);
        cudaStreamCreateWithFlags(&s3, cudaStreamNonBlocking);
        cudaEventCreateWithFlags(&evFork,  cudaEventDisableTiming);
        cudaEventCreateWithFlags(&evX,     cudaEventDisableTiming);
        cudaEventCreateWithFlags(&evW13a,  cudaEventDisableTiming);
        cudaEventCreateWithFlags(&evW13b,  cudaEventDisableTiming);
        cudaEventCreateWithFlags(&evGu0,   cudaEventDisableTiming);
        cudaEventCreateWithFlags(&evGu1,   cudaEventDisableTiming);
        cudaEventCreateWithFlags(&evDown,  cudaEventDisableTiming);
        cudaEventCreateWithFlags(&evJoin,  cudaEventDisableTiming);
    }

    const size_t W13_H = (size_t)EPH * 2 * IDIM * HDIM;   // elements per half
    const size_t W2_H  = (size_t)EPH * HDIM * IDIM;

    // fork at t=0
    cudaEventRecord(evFork, 0);
    cudaStreamWaitEvent(s2, evFork, 0);
    cudaStreamWaitEvent(s3, evFork, 0);

    // s2: interleaved weight converts, then the down lane
    cvt_k<<<8192, 256, 0, s2>>>((const float4*)w13, (uint2*)p_w13h, (long)(W13_H / 4));
    cudaEventRecord(evW13a, s2);
    cvt_k<<<4096, 256, 0, s2>>>((const float4*)w2, (uint2*)p_w2h, (long)(W2_H / 4));
    cvt_k<<<8192, 256, 0, s2>>>((const float4*)(w13 + W13_H), (uint2*)(p_w13h + W13_H),
                                (long)(W13_H / 4));
    cudaEventRecord(evW13b, s2);
    cvt_k<<<4096, 256, 0, s2>>>((const float4*)(w2 + W2_H), (uint2*)(p_w2h + W2_H),
                                (long)(W2_H / 4));

    // s0: cvt x (zeros router counts) | router | gather
    cvt_init_k<<<1024, 256>>>((const float4*)x, (uint2*)p_xh, (long)T_TOK * HDIM / 4);
    cudaEventRecord(evX, 0);
    router_fused_k<<<T_TOK, 256>>>(x, w_gate);
    gather_k<<<NROWS, 256>>>();

    // s0: gu halves (each gated by its w13 half)
    cudaStreamWaitEvent(0, evW13a, 0);
    gemm10<true, true><<<dim3(IDIM / 64, 8, EPH), 256, GS_DENSE>>>(
        tmXg, tmW13, p_h, HDIM, IDIM, 2 * IDIM, IDIM, 0, 0);
    cudaEventRecord(evGu0, 0);
    cudaStreamWaitEvent(0, evW13b, 0);
    gemm10<true, true><<<dim3(IDIM / 64, 8, EPH), 256, GS_DENSE>>>(
        tmXg, tmW13, p_h, HDIM, IDIM, 2 * IDIM, IDIM, 0, EPH);
    cudaEventRecord(evGu1, 0);

    // s2 tail: down halves (w2 cvts precede in-stream; only gu deps need events)
    cudaStreamWaitEvent(s2, evGu0, 0);
    gemm10<true, false><<<dim3(HDIM / BN, 8, EPH), 256, GS_DENSE, s2>>>(
        tmH, tmW2, p_down, IDIM, HDIM, HDIM, 0, 0, 0);
    cudaStreamWaitEvent(s2, evGu1, 0);
    gemm10<true, false><<<dim3(HDIM / BN, 8, EPH), 256, GS_DENSE, s2>>>(
        tmH, tmW2, p_down, IDIM, HDIM, HDIM, 0, 0, EPH);
    cudaEventRecord(evDown, s2);

    // s3: shared chain
    cvt_k<<<2048, 256, 0, s3>>>((const float4*)wsg, (uint2*)p_wsgh, (long)2 * SIDIM * HDIM / 4);
    cvt_k<<<2048, 256, 0, s3>>>((const float4*)wsd, (uint2*)p_wsdh, (long)HDIM * SIDIM / 4);
    cudaStreamWaitEvent(s3, evX, 0);
    gemm10<false, true ><<<dim3(SIDIM / 64, T_TOK / BM, 1), 256, GS_DENSE, s3>>>(
        tmXh, tmWsg, p_h_s, HDIM, SIDIM, 0, SIDIM, T_TOK, 0);
    gemm10<false, false><<<dim3(HDIM / BN, T_TOK / BM, 1), 256, GS_DENSE, s3>>>(
        tmHs, tmWsd, p_sh_out, SIDIM, HDIM, 0, 0, T_TOK, 0);
    cudaEventRecord(evJoin, s3);

    // s0: combine after MoE-down lane and shared lane
    cudaStreamWaitEvent(0, evDown, 0);
    cudaStreamWaitEvent(0, evJoin, 0);
    combine_k<<<T_TOK, 256>>>(out);
}

// round 17
// speedup vs baseline: 1.0831x; 1.0831x over previous
#include <cuda_runtime.h>
#include <cuda.h>
#include <cuda_fp16.h>
#include <cstdint>
#include <cmath>

// Problem constants
#define T_TOK 1024
#define HDIM  2048
#define NEXP  64
#define IDIM  1024
#define SIDIM 4096
#define KSEL  8
#define NROWS (T_TOK * KSEL)

// Tile config: CTA 128x128, 8 warps (4Mx2N), warp tile 32x64, fp16 BK=64.
#define BM 128
#define BN 128
#define NSTAGE 3
#define STG_B   32768                          // bytes per stage (A 16KB + B 16KB)
#define MBOFF   (NSTAGE * STG_B)               // 98304
#define GS_DENSE (MBOFF + 64 + 128)            // 98496

// ---------------------------------------------------------------------------
// Device-global scratch (weight fp16 buffers eliminated — in-GEMM conversion)
// ---------------------------------------------------------------------------
__device__ __align__(256) __half g_xh  [(size_t)T_TOK * HDIM];           // 4MB
__device__ __align__(256) __half g_xg  [(size_t)NROWS * HDIM];           // 32MB gathered x
__device__ __align__(256) __half g_h   [(size_t)NROWS * IDIM];           // 16MB
__device__ __align__(256) __half g_h_s [(size_t)T_TOK * SIDIM];          // 8MB
__device__ __align__(256) float  g_down[(size_t)NROWS * HDIM];           // 64MB
__device__ __align__(256) float  g_sh_out[(size_t)T_TOK * HDIM];         // 8MB

__device__ int   g_counts[NEXP];
__device__ int   g_offsets[NEXP];
__device__ int   g_fill[NEXP];
__device__ int   g_rowmap[NROWS];
__device__ int   g_row_of_tk[NROWS];
__device__ int   g_top_e[NROWS];
__device__ float g_top_w[NROWS];
__device__ int   g_ticket;

// ---------------------------------------------------------------------------
// Helpers
// ---------------------------------------------------------------------------
#define MBARRIER_INIT(addr, cnt) \
    asm volatile("mbarrier.init.shared.b64 [%0], %1;" :: "r"((uint32_t)(addr)), "r"((uint32_t)(cnt)) : "memory")

#define MBARRIER_EXPECT_TX(addr, bytes) \
    asm volatile("mbarrier.arrive.expect_tx.shared.b64 _, [%0], %1;" \
        :: "r"((uint32_t)(addr)), "r"((uint32_t)(bytes)) : "memory")

#define MBARRIER_WAIT_PARITY(addr, parity) do {                                         \
    uint32_t _m = (uint32_t)(addr); uint32_t _p = (uint32_t)(parity); uint32_t _d;      \
    asm volatile("{ .reg .pred p; mbarrier.try_wait.parity.acquire.cta.shared::cta.b64 p, [%1], %2; selp.b32 %0,1,0,p; }" \
        : "=r"(_d) : "r"(_m), "r"(_p) : "memory");                                      \
    if (!_d) {                                                                          \
        asm volatile("{ .reg .pred P1; WL_%=: mbarrier.try_wait.parity.acquire.cta.shared::cta.b64 P1, [%0], %1, 0x989680; @P1 bra.uni WD_%=; bra.uni WL_%=; WD_%=: }" \
            :: "r"(_m), "r"(_p) : "memory");                                            \
    }                                                                                   \
} while (0)

#define FENCE_ASYNC() asm volatile("fence.proxy.async.shared::cta;" ::: "memory")

__device__ __forceinline__ void tma2d(uint32_t dst, const CUtensorMap* tm, int x, int y, uint32_t mbar) {
    asm volatile("cp.async.bulk.tensor.2d.shared::cta.global.tile.mbarrier::complete_tx::bytes "
                 "[%0], [%1, {%2, %3}], [%4];"
                 :: "r"(dst), "l"(tm), "r"(x), "r"(y), "r"(mbar) : "memory");
}

__device__ __forceinline__ void ldm_x4(uint32_t& r0, uint32_t& r1, uint32_t& r2, uint32_t& r3,
                                       uint32_t addr) {
    asm volatile("ldmatrix.sync.aligned.m8n8.x4.shared.b16 {%0,%1,%2,%3}, [%4];"
                 : "=r"(r0), "=r"(r1), "=r"(r2), "=r"(r3) : "r"(addr));
}

__device__ __forceinline__ void sts64(uint32_t addr, uint32_t a, uint32_t b) {
    asm volatile("st.shared.v2.b32 [%0], {%1, %2};" :: "r"(addr), "r"(a), "r"(b));
}

__device__ __forceinline__ void mma_f16(float c[4],
                                        uint32_t a0, uint32_t a1, uint32_t a2, uint32_t a3,
                                        uint32_t b0, uint32_t b1) {
    asm volatile(
        "mma.sync.aligned.m16n8k16.row.col.f32.f16.f16.f32 "
        "{%0,%1,%2,%3},{%4,%5,%6,%7},{%8,%9},{%0,%1,%2,%3};\n"
        : "+f"(c[0]), "+f"(c[1]), "+f"(c[2]), "+f"(c[3])
        : "r"(a0), "r"(a1), "r"(a2), "r"(a3), "r"(b0), "r"(b1));
}

__device__ __forceinline__ float silu_mul(float g, float u) {
    return g * u / (1.f + expf(-g));
}

// ---------------------------------------------------------------------------
// x convert (fp32 -> fp16) with router-count init fused
// ---------------------------------------------------------------------------
__global__ void cvt_init_k(const float4* __restrict__ in, uint2* __restrict__ outp, long n4) {
    if (blockIdx.x == 0 && threadIdx.x < NEXP) g_counts[threadIdx.x] = 0;
    long i = (long)blockIdx.x * blockDim.x + threadIdx.x;
    long stride = (long)gridDim.x * blockDim.x;
    for (; i < n4; i += stride) {
        float4 v = in[i];
        __half2 h0 = __floats2half2_rn(v.x, v.y);
        __half2 h1 = __floats2half2_rn(v.z, v.w);
        uint2 o;
        o.x = *(uint32_t*)&h0;
        o.y = *(uint32_t*)&h1;
        outp[i] = o;
    }
}

// ---------------------------------------------------------------------------
// Fused router + scan + assign (ticket: last block finalizes)
// ---------------------------------------------------------------------------
__global__ void router_fused_k(const float* __restrict__ x, const float* __restrict__ wg) {
    int t = blockIdx.x;
    __shared__ float xs[HDIM];
    __shared__ float sc[NEXP];
    __shared__ int isLast;
    for (int d = threadIdx.x; d < HDIM; d += blockDim.x) xs[d] = x[(size_t)t * HDIM + d];
    __syncthreads();

    int w = threadIdx.x >> 5, lane = threadIdx.x & 31;
    for (int e = w * 8; e < w * 8 + 8; e++) {
        const float* wr = wg + (size_t)e * HDIM;
        float s = 0.f;
        for (int d = lane; d < HDIM; d += 32) s += xs[d] * wr[d];
        #pragma unroll
        for (int o = 16; o; o >>= 1) s += __shfl_xor_sync(0xffffffffu, s, o);
        if (lane == 0) sc[e] = 1.f / (1.f + expf(-s));
    }
    __syncthreads();

    if (threadIdx.x == 0) {
        for (int k = 0; k < KSEL; k++) {
            int best = 0; float bv = sc[0];
            for (int e = 1; e < NEXP; e++)
                if (sc[e] > bv) { bv = sc[e]; best = e; }
            g_top_e[t * KSEL + k] = best;
            g_top_w[t * KSEL + k] = bv;
            atomicAdd(&g_counts[best], 1);
            sc[best] = -1.f;
        }
    }

    __threadfence();
    if (threadIdx.x == 0) {
        int tk = atomicAdd(&g_ticket, 1);
        isLast = (tk == (int)gridDim.x - 1);
        if (isLast) g_ticket = 0;
    }
    __syncthreads();
    if (!isLast) return;

    if (threadIdx.x == 0) {
        int acc = 0;
        for (int e = 0; e < NEXP; e++) {
            g_offsets[e] = acc;
            g_fill[e] = acc;
            acc += g_counts[e];
        }
    }
    __syncthreads();
    for (int idx = threadIdx.x; idx < NROWS; idx += blockDim.x) {
        int e = g_top_e[idx];
        int r = atomicAdd(&g_fill[e], 1);
        g_rowmap[r] = idx >> 3;
        g_row_of_tk[idx] = r;
    }
}

// ---------------------------------------------------------------------------
// gather_k — materialize gathered A: g_xg[r] = g_xh[rowmap[r]]
// ---------------------------------------------------------------------------
__global__ void gather_k() {
    int r = blockIdx.x;
    int src = g_rowmap[r];
    const uint4* s = (const uint4*)(g_xh + (size_t)src * HDIM);
    uint4* d = (uint4*)(g_xg + (size_t)r * HDIM);
    d[threadIdx.x] = s[threadIdx.x];
}

// ---------------------------------------------------------------------------
// gemm11 — FP16 mma.sync; A via TMA (fp16, SW128 = verified c^(r&7));
// B read DIRECTLY from fp32 weights: per warp 16 rows, 8 coalesced LDG.128
// per ktile, cvt to fp16 in regs, 8 conflict-free STS.64 into the same
// swizzled layout. No weight pre-convert pass. Consumer path unchanged.
// CTA 128x128, 8 warps (4Mx2N), warp tile 32x64, BK=64, 3-stage ring.
// ---------------------------------------------------------------------------
template <bool EXPERT, bool ACT>
__global__ void __launch_bounds__(256, 1)
gemm11(const __grid_constant__ CUtensorMap tmA,
       const float* __restrict__ Bw,
       void* __restrict__ Cv,
       int Kd, int Nout, int rowsBe, int upOff, int Mdense, int eBase)
{
    extern __shared__ char sm[];
    int e = EXPERT ? (eBase + blockIdx.z) : 0;
    int M, off;
    if (EXPERT) { M = g_counts[e]; off = g_offsets[e]; }
    else        { M = Mdense;      off = 0; }
    int m0 = blockIdx.y * BM;
    if (m0 >= M) return;
    int nb = blockIdx.x;

    int tid = threadIdx.x, warp = tid >> 5, lane = tid & 31;
    uint32_t smem_base = (uint32_t)__cvta_generic_to_shared(sm);
    const CUtensorMap* tmAp = &tmA;
    int rowBase = EXPERT ? e * rowsBe : 0;
    int aRow0 = off + m0;

    if (tid == 0) {
        #pragma unroll
        for (int s = 0; s < NSTAGE; s++) MBARRIER_INIT(smem_base + MBOFF + s * 8, 1);
        FENCE_ASYNC();
    }
    __syncthreads();

    auto stage_issueA = [&](int kt, int s) {
        if (tid == 0) {
            uint32_t mb = smem_base + (uint32_t)(MBOFF + s * 8);
            uint32_t stg = smem_base + (uint32_t)(s * STG_B);
            MBARRIER_EXPECT_TX(mb, 16384);
            tma2d(stg, tmAp, kt * 64, aRow0, mb);
        }
    };

    // ---- B producer constants: warp owns local rows [warp*16, warp*16+16)
    int l16 = lane >> 4;             // 0/1: row parity within pair
    int l15 = lane & 15;             // 16B segment within 256B fp32 row-chunk
    int gbase;                       // global B row of this warp's first row
    if (ACT) gbase = (warp < 4) ? (rowBase + nb * 64 + warp * 16)
                                : (rowBase + upOff + nb * 64 + (warp - 4) * 16);
    else     gbase = rowBase + nb * BN + warp * 16;
    const float* bp = Bw + (size_t)(gbase + l16) * Kd + l15 * 4;
    int  rB   = warp * 16 + l16;     // local fp16 row (+2i per iteration)
    int  cIdx = l15 >> 1;            // 16B chunk index within 128B fp16 row
    uint32_t subo = (uint32_t)((l15 & 1) * 8);

    float4 breg[8];
    #pragma unroll
    for (int i = 0; i < 8; i++)
        breg[i] = __ldg((const float4*)(bp + (size_t)2 * i * Kd));   // B(0)

    // ---- consumer constants (verified fragment mapping)
    int wm = warp & 3;
    int wn = warp >> 2;
    int g  = lane >> 2, tg = lane & 3;

    int aro  = (lane & 7) + ((lane >> 3) & 1) * 8;
    int acs  = (lane >> 4) & 1;
    int bro  = (lane & 7) + ((lane >> 4) & 1) * 8;
    int bcs  = (lane >> 3) & 1;

    uint32_t aRow[2], aMod[2];
    #pragma unroll
    for (int mi = 0; mi < 2; mi++) {
        int r = wm * 32 + mi * 16 + aro;
        aRow[mi] = (uint32_t)(r * 128);
        aMod[mi] = (uint32_t)(r & 7);
    }
    uint32_t bRow[4], bMod[4];
    #pragma unroll
    for (int p = 0; p < 4; p++) {
        int base;
        if (ACT) base = (p < 2) ? (wn * 32 + p * 16) : (64 + wn * 32 + (p - 2) * 16);
        else     base = wn * 64 + p * 16;
        int r = base + bro;
        bRow[p] = (uint32_t)(16384 + r * 128);
        bMod[p] = (uint32_t)(r & 7);
    }

    float acc[2][8][4];
    #pragma unroll
    for (int i = 0; i < 2; i++)
        #pragma unroll
        for (int j = 0; j < 8; j++)
            #pragma unroll
            for (int q = 0; q < 4; q++) acc[i][j][q] = 0.f;

    int ktiles = Kd / 64;
    stage_issueA(0, 0);
    stage_issueA(1, 1);
    uint32_t phases = 0;

    for (int kt = 0; kt < ktiles; kt++) {
        int s = kt % NSTAGE;
        uint32_t stg = smem_base + (uint32_t)(s * STG_B);

        // convert+store B(kt) from regs into stage s (swizzled fp16)
        #pragma unroll
        for (int i = 0; i < 8; i++) {
            int rL = rB + 2 * i;
            uint32_t addr = stg + 16384u + (uint32_t)(rL * 128)
                          + ((uint32_t)(cIdx ^ (rL & 7)) << 4) + subo;
            __half2 h0 = __floats2half2_rn(breg[i].x, breg[i].y);
            __half2 h1 = __floats2half2_rn(breg[i].z, breg[i].w);
            sts64(addr, *(uint32_t*)&h0, *(uint32_t*)&h1);
        }
        // prefetch B(kt+1) (completes under the mma loop)
        if (kt + 1 < ktiles) {
            const float* src = bp + (size_t)(kt + 1) * 64;
            #pragma unroll
            for (int i = 0; i < 8; i++)
                breg[i] = __ldg((const float4*)(src + (size_t)2 * i * Kd));
        }

        uint32_t mb = smem_base + (uint32_t)(MBOFF + s * 8);
        MBARRIER_WAIT_PARITY(mb, (phases >> s) & 1);    // A(kt) arrived
        phases ^= (1u << s);
        __syncthreads();                                 // B STS visible CTA-wide

        #pragma unroll
        for (int kk = 0; kk < 4; kk++) {
            uint32_t c0 = (uint32_t)(kk * 2);

            uint32_t afr[2][4];
            #pragma unroll
            for (int mi = 0; mi < 2; mi++) {
                uint32_t addr = stg + aRow[mi] + ((((c0 + acs) ^ aMod[mi])) << 4);
                ldm_x4(afr[mi][0], afr[mi][1], afr[mi][2], afr[mi][3], addr);
            }
            uint32_t bfr[4][4];
            #pragma unroll
            for (int p = 0; p < 4; p++) {
                uint32_t addr = stg + bRow[p] + ((((c0 + bcs) ^ bMod[p])) << 4);
                ldm_x4(bfr[p][0], bfr[p][1], bfr[p][2], bfr[p][3], addr);
            }
            #pragma unroll
            for (int p = 0; p < 4; p++) {
                #pragma unroll
                for (int h = 0; h < 2; h++) {
                    int ni = p * 2 + h;
                    uint32_t b0 = bfr[p][2 * h], b1 = bfr[p][2 * h + 1];
                    mma_f16(acc[0][ni], afr[0][0], afr[0][1], afr[0][2], afr[0][3], b0, b1);
                    mma_f16(acc[1][ni], afr[1][0], afr[1][1], afr[1][2], afr[1][3], b0, b1);
                }
            }
        }
        __syncthreads();                                 // all reads of stage s done
        if (kt + 2 < ktiles) stage_issueA(kt + 2, (kt + 2) % NSTAGE);
    }

    // ---- epilogue
    #pragma unroll
    for (int mi = 0; mi < 2; mi++) {
        int r0 = m0 + wm * 32 + mi * 16 + g;
        bool v0 = r0 < M, v1 = (r0 + 8) < M;
        size_t base0 = (size_t)(off + r0) * Nout;
        size_t base1 = (size_t)(off + r0 + 8) * Nout;
        if (ACT) {
            __half* Ch = (__half*)Cv;
            #pragma unroll
            for (int ni = 0; ni < 4; ni++) {
                int col = nb * 64 + wn * 32 + ni * 8 + tg * 2;
                if (v0) {
                    __half2 o = __floats2half2_rn(
                        silu_mul(acc[mi][ni][0], acc[mi][ni + 4][0]),
                        silu_mul(acc[mi][ni][1], acc[mi][ni + 4][1]));
                    *(__half2*)(Ch + base0 + col) = o;
                }
                if (v1) {
                    __half2 o = __floats2half2_rn(
                        silu_mul(acc[mi][ni][2], acc[mi][ni + 4][2]),
                        silu_mul(acc[mi][ni][3], acc[mi][ni + 4][3]));
                    *(__half2*)(Ch + base1 + col) = o;
                }
            }
        } else {
            float* Cf = (float*)Cv;
            #pragma unroll
            for (int ni = 0; ni < 8; ni++) {
                int col = nb * BN + wn * 64 + ni * 8 + tg * 2;
                if (v0) {
                    float2 o; o.x = acc[mi][ni][0]; o.y = acc[mi][ni][1];
                    *(float2*)(Cf + base0 + col) = o;
                }
                if (v1) {
                    float2 o; o.x = acc[mi][ni][2]; o.y = acc[mi][ni][3];
                    *(float2*)(Cf + base1 + col) = o;
                }
            }
        }
    }
}

// ---------------------------------------------------------------------------
// Combine
// ---------------------------------------------------------------------------
__global__ void combine_k(float* __restrict__ out) {
    int t = blockIdx.x;
    __shared__ int   rws[KSEL];
    __shared__ float ws[KSEL];
    if (threadIdx.x < KSEL) {
        rws[threadIdx.x] = g_row_of_tk[t * KSEL + threadIdx.x];
        ws[threadIdx.x]  = g_top_w[t * KSEL + threadIdx.x];
    }
    __syncthreads();
    for (int d = threadIdx.x; d < HDIM; d += blockDim.x) {
        float a = g_sh_out[(size_t)t * HDIM + d];
        float m = 0.f;
        #pragma unroll
        for (int k = 0; k < KSEL; k++)
            m += ws[k] * g_down[(size_t)rws[k] * HDIM + d];
        out[(size_t)t * HDIM + d] = (a + 8.f * m) * (1.f / 9.f);
    }
}

// ---------------------------------------------------------------------------
// kernel_launch — graph-capturable, allocation-free, TWO-stream DAG
// (9 kernels, 3 events — minimal graph):
//  s0: cvt_x | router | gather | gu(all) | down(all) | [join] combine
//  s3: [x] sh_gu | sh_down | join
// ---------------------------------------------------------------------------
typedef CUresult (CUDAAPI *PFN_encodeTiled)(
    CUtensorMap*, CUtensorMapDataType, cuuint32_t, void*,
    const cuuint64_t*, const cuuint64_t*, const cuuint32_t*, const cuuint32_t*,
    CUtensorMapInterleave, CUtensorMapSwizzle, CUtensorMapL2promotion,
    CUtensorMapFloatOOBfill);

extern "C" void kernel_launch(void* const* d_in, const int* in_sizes, int n_in,
                              void* d_out, int out_size)
{
    const float* x      = (const float*)d_in[0];
    const float* w_gate = (const float*)d_in[1];
    const float* w13    = (const float*)d_in[2];
    const float* w2     = (const float*)d_in[3];
    const float* wsg    = (const float*)d_in[4];
    const float* wsd    = (const float*)d_in[5];
    float* out = (float*)d_out;

    __half *p_xh, *p_xg, *p_h, *p_h_s;
    float  *p_down, *p_sh_out;
    cudaGetSymbolAddress((void**)&p_xh,     g_xh);
    cudaGetSymbolAddress((void**)&p_xg,     g_xg);
    cudaGetSymbolAddress((void**)&p_h,      g_h);
    cudaGetSymbolAddress((void**)&p_h_s,    g_h_s);
    cudaGetSymbolAddress((void**)&p_down,   g_down);
    cudaGetSymbolAddress((void**)&p_sh_out, g_sh_out);

    static bool tmInit = false;
    static CUtensorMap tmXh, tmXg, tmH, tmHs;
    if (!tmInit) {
        PFN_encodeTiled enc = nullptr;
        cudaDriverEntryPointQueryResult qr;
        cudaGetDriverEntryPoint("cuTensorMapEncodeTiled", (void**)&enc, cudaEnableDefault, &qr);
        auto mk = [&](CUtensorMap* tm, void* ptr, unsigned long long d0, unsigned long long d1) {
            cuuint64_t dims[2]    = {d0, d1};
            cuuint64_t strides[1] = {d0 * 2};
            cuuint32_t box[2]     = {64, 128};
            cuuint32_t es[2]      = {1, 1};
            enc(tm, CU_TENSOR_MAP_DATA_TYPE_FLOAT16, 2, ptr, dims, strides, box, es,
                CU_TENSOR_MAP_INTERLEAVE_NONE, CU_TENSOR_MAP_SWIZZLE_128B,
                CU_TENSOR_MAP_L2_PROMOTION_L2_128B, CU_TENSOR_MAP_FLOAT_OOB_FILL_NONE);
        };
        mk(&tmXh, p_xh,  HDIM,  T_TOK);
        mk(&tmXg, p_xg,  HDIM,  NROWS);
        mk(&tmH,  p_h,   IDIM,  NROWS);
        mk(&tmHs, p_h_s, SIDIM, T_TOK);
        tmInit = true;
    }

    cudaFuncSetAttribute(gemm11<true,  true >, cudaFuncAttributeMaxDynamicSharedMemorySize, GS_DENSE);
    cudaFuncSetAttribute(gemm11<true,  false>, cudaFuncAttributeMaxDynamicSharedMemorySize, GS_DENSE);
    cudaFuncSetAttribute(gemm11<false, true >, cudaFuncAttributeMaxDynamicSharedMemorySize, GS_DENSE);
    cudaFuncSetAttribute(gemm11<false, false>, cudaFuncAttributeMaxDynamicSharedMemorySize, GS_DENSE);

    static cudaStream_t s3 = nullptr;
    static cudaEvent_t evFork = nullptr, evX = nullptr, evJoin = nullptr;
    if (!s3) {
        cudaStreamCreateWithFlags(&s3, cudaStreamNonBlocking);
        cudaEventCreateWithFlags(&evFork, cudaEventDisableTiming);
        cudaEventCreateWithFlags(&evX,    cudaEventDisableTiming);
        cudaEventCreateWithFlags(&evJoin, cudaEventDisableTiming);
    }

    cudaEventRecord(evFork, 0);
    cudaStreamWaitEvent(s3, evFork, 0);

    // s0: x convert (zeros router counts) | router | gather
    cvt_init_k<<<1024, 256>>>((const float4*)x, (uint2*)p_xh, (long)T_TOK * HDIM / 4);
    cudaEventRecord(evX, 0);
    router_fused_k<<<T_TOK, 256>>>(x, w_gate);
    gather_k<<<NROWS, 256>>>();

    // s0 #4 (ncu slot): MoE gate_up, all experts, fp32 weights read in-kernel
    gemm11<true, true><<<dim3(IDIM / 64, 8, NEXP), 256, GS_DENSE>>>(
        tmXg, w13, p_h, HDIM, IDIM, 2 * IDIM, IDIM, 0, 0);

    // s0 #5: MoE down
    gemm11<true, false><<<dim3(HDIM / BN, 8, NEXP), 256, GS_DENSE>>>(
        tmH, w2, p_down, IDIM, HDIM, HDIM, 0, 0, 0);

    // s3: shared chain (needs only xh)
    cudaStreamWaitEvent(s3, evX, 0);
    gemm11<false, true ><<<dim3(SIDIM / 64, T_TOK / BM, 1), 256, GS_DENSE, s3>>>(
        tmXh, wsg, p_h_s, HDIM, SIDIM, 0, SIDIM, T_TOK, 0);
    gemm11<false, false><<<dim3(HDIM / BN, T_TOK / BM, 1), 256, GS_DENSE, s3>>>(
        tmHs, wsd, p_sh_out, SIDIM, HDIM, 0, 0, T_TOK, 0);
    cudaEventRecord(evJoin, s3);

    // s0: combine
    cudaStreamWaitEvent(0, evJoin, 0);
    combine_k<<<T_TOK, 256>>>(out);
}